// round 16
// baseline (speedup 1.0000x reference)
#include <cuda_runtime.h>
#include <cuda_fp16.h>
#include <cstdint>
#include <cstddef>

// ============================================================================
// Problem constants
// ============================================================================
static constexpr int BATCH  = 16384;
static constexpr int IN_DIM = 512;
static constexpr int UNITS  = 256;
static constexpr int NEXP   = 8;
static constexpr int NTASK  = 4;
static constexpr int NCOL   = UNITS * NEXP;   // 2048, n = u*8+e
static constexpr int GCOL   = NEXP * NTASK;   // 32,   g = e*4+t

// Fragment-block geometry (mma.m16n8k16.f16)
static constexpr int MBLKS  = BATCH / 16;     // 1024
static constexpr int KB16   = IN_DIM / 16;    // 32  (A k-blocks)
static constexpr int KB32   = IN_DIM / 32;    // 16  (B k-block pairs)
static constexpr int NBLKS  = NCOL / 8;       // 256
static constexpr int GNBLKS = GCOL / 8;       // 4

// Tiling: 4 warps of 64x64, KC=64 (half the barrier count)
static constexpr int BM     = 128;            // 8 m_blks -> 2048 CTAs
static constexpr int BN     = 128;            // 16 n_blks
static constexpr int KC     = 64;             // 4 k16 / 2 k32 per stage
static constexpr int KSTEPS = IN_DIM / KC;    // 8
static constexpr int STAGES = 3;
static constexpr int NTHREADS = 128;          // 4 warps, 2(m) x 2(n), 64x64 tiles

// Shared memory (uint4 units): stage = A(8*4*32) + B(16*2*32) = 2048 u4 = 32KB
static constexpr int A_STAGE_U4 = 8 * 4 * 32;     // 1024
static constexpr int B_STAGE_U4 = 16 * 2 * 32;    // 1024
static constexpr int STAGE_U4   = A_STAGE_U4 + B_STAGE_U4;  // 2048
static constexpr int HDR_U4     = 32;             // be slice (128 floats)
static constexpr int SMEM_U4    = HDR_U4 + STAGES * STAGE_U4;
static constexpr int SMEM_BYTES = SMEM_U4 * 16;   // 98816 (x2 CTA = 193 KB)
static constexpr int C_LD       = BN + 4;         // 132 (staging 128*132*4 = 67.6 KB, fits)

// ============================================================================
// Device scratch (no allocations allowed)
// ============================================================================
__device__ float g_gates[BATCH * GCOL];                  // softmaxed gates
__device__ uint4 g_xA [(size_t)MBLKS * KB16 * 32];       // A frags fp16 (16 MB)
__device__ uint4 g_WeB[(size_t)NBLKS * KB32 * 32];       // We B frags  ( 2 MB)
__device__ uint4 g_WgB[(size_t)GNBLKS * KB32 * 32];      // Wg B frags  (32 KB)

// ============================================================================
// Helpers
// ============================================================================
__device__ __forceinline__ uint32_t smem_u32(const void* p) {
    uint32_t a;
    asm("{ .reg .u64 t; cvta.to.shared.u64 t, %1; cvt.u32.u64 %0, t; }" : "=r"(a) : "l"(p));
    return a;
}
__device__ __forceinline__ uint32_t pack_h2(float lo, float hi) {
    __half2 h = __floats2half2_rn(lo, hi);
    return *(uint32_t*)&h;
}
__device__ __forceinline__ void cp_async16(uint32_t dst, const void* src) {
    asm volatile("cp.async.cg.shared.global [%0], [%1], 16;\n" :: "r"(dst), "l"(src));
}
#define CP_COMMIT()       asm volatile("cp.async.commit_group;\n" ::: "memory")
#define CP_WAIT_GROUP_1() asm volatile("cp.async.wait_group 1;\n" ::: "memory")

// D += A(16x16) * B(16x8), fp16 operands, f32 accum
__device__ __forceinline__ void mma_f16(float* c, const uint4& a, uint32_t b0, uint32_t b1) {
    asm volatile(
        "mma.sync.aligned.m16n8k16.row.col.f32.f16.f16.f32 "
        "{%0,%1,%2,%3}, {%4,%5,%6,%7}, {%8,%9}, {%0,%1,%2,%3};"
        : "+f"(c[0]), "+f"(c[1]), "+f"(c[2]), "+f"(c[3])
        : "r"(a.x), "r"(a.y), "r"(a.z), "r"(a.w), "r"(b0), "r"(b1));
}

// ============================================================================
// prep Wg: pack Wg into fp16 B-fragment order (2048 u4 slots)
// ============================================================================
__global__ void __launch_bounds__(128)
prep_Wg_kernel(const float* __restrict__ Wg) {
    int slot = blockIdx.x * 128 + threadIdx.x;   // 16 blocks x 128 = 2048
    int gn   = slot >> 9;
    int rem  = slot & 511;
    int kb32 = rem >> 5;
    int ln   = rem & 31;
    int g2 = ln >> 2, t2 = ln & 3;
    int n  = gn * 8 + g2;
    int kb = kb32 * 32;
    uint4 v;
    v.x = pack_h2(__ldg(Wg + (size_t)(kb + 2*t2)      * GCOL + n),
                  __ldg(Wg + (size_t)(kb + 2*t2 + 1)  * GCOL + n));
    v.y = pack_h2(__ldg(Wg + (size_t)(kb + 2*t2 + 8)  * GCOL + n),
                  __ldg(Wg + (size_t)(kb + 2*t2 + 9)  * GCOL + n));
    v.z = pack_h2(__ldg(Wg + (size_t)(kb + 2*t2 + 16) * GCOL + n),
                  __ldg(Wg + (size_t)(kb + 2*t2 + 17) * GCOL + n));
    v.w = pack_h2(__ldg(Wg + (size_t)(kb + 2*t2 + 24) * GCOL + n),
                  __ldg(Wg + (size_t)(kb + 2*t2 + 25) * GCOL + n));
    g_WgB[slot] = v;
}

// ============================================================================
// Gate kernel: x fp16 A-fragment pack + tensor-core gate logits + softmax.
// Also packs a uniform 128-slot slice of We B-fragments per block.
// ============================================================================
static constexpr int XS_LD = IN_DIM + 4;   // 516

__global__ void __launch_bounds__(512)
gate_kernel(const float4* __restrict__ x4, const float* __restrict__ bg,
            const float* __restrict__ We) {
    __shared__ float xs[16][XS_LD];        // 33 KB
    __shared__ float ls[16][GCOL];         //  2 KB
    const int tid  = threadIdx.x;
    const int wid  = tid >> 5;
    const int lane = tid & 31;
    const int gr   = lane >> 2, tig = lane & 3;
    const int blk  = blockIdx.x;           // m_blk
    const int b0   = blk * 16;

    // Uniform We B-fragment pack slice: 128 slots for this block.
    if (tid < 128) {
        int s    = blk * 128 + tid;        // flat g_WeB index
        int rem  = s & 511;
        int kb32 = rem >> 5;
        int ln   = rem & 31;
        int g2 = ln >> 2, t2 = ln & 3;
        int n  = (s >> 9) * 8 + g2;
        int kb = kb32 * 32;
        uint4 v;
        v.x = pack_h2(__ldg(We + (size_t)(kb + 2*t2)      * NCOL + n),
                      __ldg(We + (size_t)(kb + 2*t2 + 1)  * NCOL + n));
        v.y = pack_h2(__ldg(We + (size_t)(kb + 2*t2 + 8)  * NCOL + n),
                      __ldg(We + (size_t)(kb + 2*t2 + 9)  * NCOL + n));
        v.z = pack_h2(__ldg(We + (size_t)(kb + 2*t2 + 16) * NCOL + n),
                      __ldg(We + (size_t)(kb + 2*t2 + 17) * NCOL + n));
        v.w = pack_h2(__ldg(We + (size_t)(kb + 2*t2 + 24) * NCOL + n),
                      __ldg(We + (size_t)(kb + 2*t2 + 25) * NCOL + n));
        g_WeB[s] = v;
    }

    // load x tile into smem
    #pragma unroll
    for (int i = 0; i < 4; i++) {
        int idx = tid + i * 512;
        int rr = idx >> 7, c = idx & 127;
        float4 v = x4[(size_t)(b0 + rr) * (IN_DIM / 4) + c];
        *(float4*)&xs[rr][c * 4] = v;
    }
    __syncthreads();

    // write fp16 A fragments to gmem (1024 slots = 32 k16 x 32 lanes)
    #pragma unroll
    for (int i = 0; i < 2; i++) {
        int slot = tid + i * 512;
        int k16  = slot >> 5;
        int ln   = slot & 31;
        int g2 = ln >> 2, t2 = ln & 3;
        int kc = k16 * 16;
        uint4 v;
        v.x = pack_h2(xs[g2][kc + 2*t2],         xs[g2][kc + 2*t2 + 1]);
        v.y = pack_h2(xs[g2 + 8][kc + 2*t2],     xs[g2 + 8][kc + 2*t2 + 1]);
        v.z = pack_h2(xs[g2][kc + 2*t2 + 8],     xs[g2][kc + 2*t2 + 9]);
        v.w = pack_h2(xs[g2 + 8][kc + 2*t2 + 8], xs[g2 + 8][kc + 2*t2 + 9]);
        g_xA[((size_t)blk * KB16 + k16) * 32 + ln] = v;
    }
    __syncthreads();   // own-block global writes now visible to this block

    // gate logits via fp16 tensor cores: warps 0..3, one gate n-blk each
    if (wid < GNBLKS) {
        float a[4] = {0.f, 0.f, 0.f, 0.f};
        const uint4* WgB = g_WgB + (size_t)wid * KB32 * 32;
        const uint4* xA  = g_xA + (size_t)blk * KB16 * 32;
        #pragma unroll 4
        for (int kb32 = 0; kb32 < KB32; kb32++) {
            uint4 Bv  = WgB[kb32 * 32 + lane];
            uint4 Av0 = xA[(kb32 * 2) * 32 + lane];
            uint4 Av1 = xA[(kb32 * 2 + 1) * 32 + lane];
            mma_f16(a, Av0, Bv.x, Bv.y);
            mma_f16(a, Av1, Bv.z, Bv.w);
        }
        ls[gr][wid * 8 + 2 * tig]         = a[0];
        ls[gr][wid * 8 + 2 * tig + 1]     = a[1];
        ls[gr + 8][wid * 8 + 2 * tig]     = a[2];
        ls[gr + 8][wid * 8 + 2 * tig + 1] = a[3];
    }
    __syncthreads();

    // softmax over experts, per (row, task)
    if (tid < 64) {
        const int rr = tid >> 2, t = tid & 3;
        float v[NEXP], m = -3.4e38f;
        #pragma unroll
        for (int e = 0; e < NEXP; e++) {
            v[e] = ls[rr][e * 4 + t] + bg[e * 4 + t];
            m = fmaxf(m, v[e]);
        }
        float den = 0.f;
        #pragma unroll
        for (int e = 0; e < NEXP; e++) { v[e] = expf(v[e] - m); den += v[e]; }
        const float inv = 1.f / den;
        #pragma unroll
        for (int e = 0; e < NEXP; e++)
            g_gates[(size_t)(b0 + rr) * GCOL + e * 4 + t] = v[e] * inv;
    }
}

// ============================================================================
// Main kernel: mma.m16n8k16 fp16, 64x64 warp tiles, KC=64 (8 iterations)
// ============================================================================
__global__ void __launch_bounds__(NTHREADS, 2)
moe_mma_kernel(const float* __restrict__ be, float* __restrict__ out) {
    extern __shared__ uint4 smem4[];
    float* sbe    = (float*)smem4;
    uint4* stage0 = smem4 + HDR_U4;

    const int tid  = threadIdx.x;
    const int wid  = tid >> 5;
    const int lane = tid & 31;
    const int gr   = lane >> 2, tig = lane & 3;
    const int warp_m = wid >> 1;        // 0..1 -> rows warp_m*64
    const int warp_n = wid & 1;         // 0..1 -> cols warp_n*64

    const int n_tile = blockIdx.x & 15;
    const int b_tile = blockIdx.x >> 4;
    const int b0  = b_tile * BM;
    const int mb0 = b_tile * 8;         // global m_blk base
    const int nb0 = n_tile * 16;        // global n_blk base

    if (tid < BN) sbe[tid] = be[n_tile * BN + tid];

    float acc[4][8][4];                 // [mi][ni][frag] = 128 regs
    #pragma unroll
    for (int mi = 0; mi < 4; mi++)
        #pragma unroll
        for (int ni = 0; ni < 8; ni++)
            #pragma unroll
            for (int q = 0; q < 4; q++) acc[mi][ni][q] = 0.f;

    auto load_stage = [&](int slot, int kt) {
        uint4* As = stage0 + slot * STAGE_U4;
        uint4* Bs = As + A_STAGE_U4;
        const uint32_t aB = smem_u32(As);
        const uint32_t bB = smem_u32(Bs);
        // A: 1024 chunks; c = (mb_l*4 + k16_l)*32 + lane -> 8 per thread
        #pragma unroll
        for (int i = 0; i < 8; i++) {
            int c = tid + i * 128;
            int mb = c >> 7, rem = c & 127;
            size_t g = ((size_t)(mb0 + mb) * KB16 + (kt * 4 + (rem >> 5))) * 32 + (rem & 31);
            cp_async16(aB + (uint32_t)c * 16, g_xA + g);
        }
        // B: 1024 chunks; c = (nb_l*2 + kb32_l)*32 + lane -> 8 per thread
        #pragma unroll
        for (int i = 0; i < 8; i++) {
            int c = tid + i * 128;
            int nb = c >> 6, rem = c & 63;
            size_t g = ((size_t)(nb0 + nb) * KB32 + (kt * 2 + (rem >> 5))) * 32 + (rem & 31);
            cp_async16(bB + (uint32_t)c * 16, g_WeB + g);
        }
    };

    auto compute_stage = [&](int slot) {
        const uint4* As = stage0 + slot * STAGE_U4;
        const uint4* Bs = As + A_STAGE_U4;
        #pragma unroll
        for (int kb32 = 0; kb32 < 2; kb32++) {
            uint4 Bv[8];
            #pragma unroll
            for (int ni = 0; ni < 8; ni++)
                Bv[ni] = Bs[((warp_n * 8 + ni) * 2 + kb32) * 32 + lane];
            #pragma unroll
            for (int h = 0; h < 2; h++) {
                const int k16 = kb32 * 2 + h;
                uint4 Av[4];
                #pragma unroll
                for (int mi = 0; mi < 4; mi++)
                    Av[mi] = As[((warp_m * 4 + mi) * 4 + k16) * 32 + lane];
                #pragma unroll
                for (int mi = 0; mi < 4; mi++)
                    #pragma unroll
                    for (int ni = 0; ni < 8; ni++) {
                        if (h == 0) mma_f16(acc[mi][ni], Av[mi], Bv[ni].x, Bv[ni].y);
                        else        mma_f16(acc[mi][ni], Av[mi], Bv[ni].z, Bv[ni].w);
                    }
            }
        }
    };

    // Prologue: fill 2 of 3 stages
    load_stage(0, 0); CP_COMMIT();
    load_stage(1, 1); CP_COMMIT();

    // Main loop (8 iterations)
    for (int kt = 0; kt < KSTEPS; kt++) {
        CP_WAIT_GROUP_1();
        __syncthreads();
        const int next = kt + 2;
        if (next < KSTEPS) load_stage(next % STAGES, next);
        CP_COMMIT();
        compute_stage(kt % STAGES);
    }

    // ------------------------------------------------------------------
    // Epilogue: single-pass C staging (67.6 KB fits the 96 KB stage region)
    // ------------------------------------------------------------------
    __syncthreads();
    float* Cs = (float*)stage0;
    #pragma unroll
    for (int mi = 0; mi < 4; mi++) {
        #pragma unroll
        for (int ni = 0; ni < 8; ni++) {
            int row = warp_m * 64 + mi * 16 + gr;
            int col = warp_n * 64 + ni * 8 + 2 * tig;
            *(float2*)&Cs[row * C_LD + col]       = make_float2(acc[mi][ni][0], acc[mi][ni][1]);
            *(float2*)&Cs[(row + 8) * C_LD + col] = make_float2(acc[mi][ni][2], acc[mi][ni][3]);
        }
    }
    __syncthreads();

    const int r = tid;            // row in tile (0..127), one row per thread
    const int b = b0 + r;

    float gate[GCOL];
    {
        const float4* gp = (const float4*)(g_gates + (size_t)b * GCOL);
        #pragma unroll
        for (int q = 0; q < 8; q++) ((float4*)gate)[q] = gp[q];
    }

    float accu[16][NTASK];
    #pragma unroll
    for (int u = 0; u < 16; u++)
        #pragma unroll
        for (int t = 0; t < NTASK; t++) accu[u][t] = 0.f;

    #pragma unroll
    for (int u = 0; u < 16; u++) {
        const int nl = u * 8;
        #pragma unroll
        for (int e = 0; e < NEXP; e++) {
            float v = Cs[r * C_LD + nl + e] + sbe[nl + e];
            v = fmaxf(v, 0.f);
            #pragma unroll
            for (int t = 0; t < NTASK; t++) accu[u][t] += v * gate[e * 4 + t];
        }
    }

    float* ob = out + (size_t)b * UNITS + n_tile * 16;
    #pragma unroll
    for (int t = 0; t < NTASK; t++) {
        #pragma unroll
        for (int q = 0; q < 4; q++) {
            float4 o = make_float4(accu[q * 4 + 0][t], accu[q * 4 + 1][t],
                                   accu[q * 4 + 2][t], accu[q * 4 + 3][t]);
            *(float4*)(ob + (size_t)t * BATCH * UNITS + q * 4) = o;
        }
    }
}

// ============================================================================
// Launch
// ============================================================================
extern "C" void kernel_launch(void* const* d_in, const int* in_sizes, int n_in,
                              void* d_out, int out_size) {
    const float* x  = (const float*)d_in[0];
    const float* We = (const float*)d_in[1];
    const float* be = (const float*)d_in[2];
    const float* Wg = (const float*)d_in[3];
    const float* bg = (const float*)d_in[4];
    float* out = (float*)d_out;

    cudaFuncSetAttribute(moe_mma_kernel, cudaFuncAttributeMaxDynamicSharedMemorySize, SMEM_BYTES);

    prep_Wg_kernel<<<16, 128>>>(Wg);
    gate_kernel<<<MBLKS, 512>>>((const float4*)x, bg, We);
    moe_mma_kernel<<<(BATCH / BM) * (NCOL / BN), NTHREADS, SMEM_BYTES>>>(be, out);
}